// round 8
// baseline (speedup 1.0000x reference)
#include <cuda_runtime.h>
#include <cstdint>
#include <cstddef>

// Problem shape (fixed)
#define BB 8
#define NN 4096
#define EE 2048
#define CC 128

// Scratch (no cudaMalloc allowed)
__device__ float g_E[BB * EE * CC];   // e (edge features), produced by fused s1

// GEMM tiling
#define BM 128
#define BN 128
#define BK 32
#define LDKM 136   // As stored [k][m], pad 8 (≡8 mod 32) -> conflict-free a-frag loads
#define LDMK 36    // As stored [m][k], pad 4 (≡4 mod 32) -> conflict-free a-frag loads
#define LDB_ 136   // Bs stored [k][n], pad 8 -> conflict-free b-frag loads
#define LDZ  132   // epilogue z smem [m][k], K=128, pad 4
#define LDW  136   // epilogue W smem [k][n], pad 8

// Threads: 512 = 16 warps, warp grid 4(m) x 4(n); each warp computes 32x32.
#define NT 512

__device__ __forceinline__ float tf32r(float x) {
    uint32_t u;
    asm("cvt.rna.tf32.f32 %0, %1;" : "=r"(u) : "f"(x));
    return __uint_as_float(u);
}

__device__ __forceinline__ void mma8(float& d0, float& d1, float& d2, float& d3,
                                     uint32_t a0, uint32_t a1, uint32_t a2, uint32_t a3,
                                     uint32_t b0, uint32_t b1) {
    asm volatile(
        "mma.sync.aligned.m16n8k8.row.col.f32.tf32.tf32.f32 "
        "{%0,%1,%2,%3},{%4,%5,%6,%7},{%8,%9},{%0,%1,%2,%3};"
        : "+f"(d0), "+f"(d1), "+f"(d2), "+f"(d3)
        : "r"(a0), "r"(a1), "r"(a2), "r"(a3), "r"(b0), "r"(b1));
}

// ===========================================================================
// S1 (fused with S2):
//   z[b,e,:] = sum_n H[b,n,e] * x[b,n,:]       (A = H^T, tensor cores)
//   se[b,e]  = sum_n H[b,n,e]                  (free from A-fragments)
//   e[b,e,:] = se>0 ? (z/se) @ W + bias : 0    (epilogue GEMM, K=128)
// ===========================================================================
__global__ void __launch_bounds__(NT, 1)
s1_kernel(const float* __restrict__ H, const float* __restrict__ X,
          const float* __restrict__ Wm, const float* __restrict__ bias) {
    const int b  = blockIdx.y;
    const int e0 = blockIdx.x * BM;

    extern __shared__ float sm[];
    // main loop overlay
    float* As = sm;                       // 2 * BK * LDKM  ([k][m])
    float* Bs = sm + 2 * BK * LDKM;       // 2 * BK * LDB_  ([k][n])
    // epilogue overlay (reuses the same bytes)
    float* zsm = sm;                      // BM * LDZ   ([m][k])  16896 floats
    float* wsm = sm + BM * LDZ;           // CC * LDW   ([k][n])  17408 floats
    __shared__ float s_rs[BM];
    __shared__ float s_inv[BM];
    __shared__ float s_b[CC];

    const int tid = threadIdx.x;
    const int lane = tid & 31, wid = tid >> 5;
    const int g = lane >> 2, tg = lane & 3;
    const int wm = (wid >> 2) * 32;       // 4 m-groups
    const int wn = (wid & 3) * 32;        // 4 n-groups

    if (tid < CC) s_b[tid] = bias[tid];

    const float* Hb = H + (size_t)b * NN * EE;
    const float* Xb = X + (size_t)b * NN * CC;

    float acc[2][4][4];
#pragma unroll
    for (int i = 0; i < 2; i++)
#pragma unroll
        for (int j = 0; j < 4; j++)
#pragma unroll
            for (int k = 0; k < 4; k++) acc[i][j][k] = 0.f;
    float rs[2][2] = {{0.f, 0.f}, {0.f, 0.f}};

    float4 ar[2], br[2];

    auto LDGA = [&](int n0) {
#pragma unroll
        for (int i = 0; i < 2; i++) {
            int idx = tid + i * NT;
            int k = idx >> 5, m4 = idx & 31;
            ar[i] = *reinterpret_cast<const float4*>(Hb + (size_t)(n0 + k) * EE + e0 + m4 * 4);
        }
    };
    auto LDGB = [&](int n0) {
#pragma unroll
        for (int i = 0; i < 2; i++) {
            int idx = tid + i * NT;
            int k = idx >> 5, c4 = idx & 31;
            br[i] = *reinterpret_cast<const float4*>(Xb + (size_t)(n0 + k) * CC + c4 * 4);
        }
    };
    auto STS = [&](int buf) {
        float* Ad = As + buf * BK * LDKM;
        float* Bd = Bs + buf * BK * LDB_;
#pragma unroll
        for (int i = 0; i < 2; i++) {
            int idx = tid + i * NT;
            int k = idx >> 5, m4 = idx & 31;
            *reinterpret_cast<float4*>(Ad + k * LDKM + m4 * 4) = ar[i];  // H exact, no cvt
            float4 v = br[i];
            v.x = tf32r(v.x); v.y = tf32r(v.y); v.z = tf32r(v.z); v.w = tf32r(v.w);
            *reinterpret_cast<float4*>(Bd + k * LDB_ + m4 * 4) = v;
        }
    };
    auto COMPUTE = [&](int buf) {
        const float* Ab = As + buf * BK * LDKM;
        const float* Bb = Bs + buf * BK * LDB_;
#pragma unroll
        for (int kk = 0; kk < BK; kk += 8) {
            uint32_t af[2][4];
#pragma unroll
            for (int mt = 0; mt < 2; mt++) {
                const float* ap = Ab + (kk + tg) * LDKM + wm + mt * 16 + g;
                af[mt][0] = __float_as_uint(ap[0]);
                af[mt][1] = __float_as_uint(ap[8]);
                af[mt][2] = __float_as_uint(ap[4 * LDKM]);
                af[mt][3] = __float_as_uint(ap[4 * LDKM + 8]);
            }
            if ((wid & 3) == 0) {  // count each H element once (wn==0 warps)
#pragma unroll
                for (int mt = 0; mt < 2; mt++) {
                    rs[mt][0] += __uint_as_float(af[mt][0]) + __uint_as_float(af[mt][2]);
                    rs[mt][1] += __uint_as_float(af[mt][1]) + __uint_as_float(af[mt][3]);
                }
            }
#pragma unroll
            for (int nt = 0; nt < 4; nt++) {
                const float* bp = Bb + (kk + tg) * LDB_ + wn + nt * 8 + g;
                uint32_t b0 = __float_as_uint(bp[0]);
                uint32_t b1 = __float_as_uint(bp[4 * LDB_]);
                mma8(acc[0][nt][0], acc[0][nt][1], acc[0][nt][2], acc[0][nt][3],
                     af[0][0], af[0][1], af[0][2], af[0][3], b0, b1);
                mma8(acc[1][nt][0], acc[1][nt][1], acc[1][nt][2], acc[1][nt][3],
                     af[1][0], af[1][1], af[1][2], af[1][3], b0, b1);
            }
        }
    };

    LDGA(0); LDGB(0); STS(0); __syncthreads();
    int buf = 0;
    const int KT = NN / BK;
    for (int kt = 0; kt < KT; kt++) {
        if (kt + 1 < KT) { LDGA((kt + 1) * BK); LDGB((kt + 1) * BK); }
        COMPUTE(buf);
        if (kt + 1 < KT) {
            STS(buf ^ 1);
            __syncthreads();
            buf ^= 1;
        }
    }

    // se: quad-reduce row sums (only wn==0 warps carried them)
    if ((wid & 3) == 0) {
#pragma unroll
        for (int mt = 0; mt < 2; mt++)
#pragma unroll
            for (int j = 0; j < 2; j++) {
                float v = rs[mt][j];
                v += __shfl_xor_sync(0xffffffff, v, 1);
                v += __shfl_xor_sync(0xffffffff, v, 2);
                if (tg == 0) s_rs[wm + mt * 16 + j * 8 + g] = v;
            }
    }
    __syncthreads();
    if (tid < BM) {
        float s = s_rs[tid];
        s_inv[tid] = (s > 0.f) ? (1.0f / s) : 0.f;
    }
    __syncthreads();   // also: all warps done reading As/Bs before overlay reuse

    // ---- epilogue stage 1: z/se -> zsm (tf32), W -> wsm (tf32) ----
#pragma unroll
    for (int mt = 0; mt < 2; mt++) {
        int r0 = wm + mt * 16 + g;
        float i0 = s_inv[r0], i1 = s_inv[r0 + 8];
#pragma unroll
        for (int nt = 0; nt < 4; nt++) {
            int col = wn + nt * 8 + 2 * tg;
            float2 v0 = make_float2(tf32r(acc[mt][nt][0] * i0), tf32r(acc[mt][nt][1] * i0));
            float2 v1 = make_float2(tf32r(acc[mt][nt][2] * i1), tf32r(acc[mt][nt][3] * i1));
            *reinterpret_cast<float2*>(zsm + r0 * LDZ + col) = v0;
            *reinterpret_cast<float2*>(zsm + (r0 + 8) * LDZ + col) = v1;
        }
    }
#pragma unroll
    for (int i = 0; i < (CC * CC / 4) / NT; i++) {   // 8 iters
        int idx = tid + i * NT;
        int k = idx >> 5, n4 = idx & 31;
        float4 w = *reinterpret_cast<const float4*>(Wm + (size_t)k * CC + n4 * 4);
        w.x = tf32r(w.x); w.y = tf32r(w.y); w.z = tf32r(w.z); w.w = tf32r(w.w);
        *reinterpret_cast<float4*>(wsm + k * LDW + n4 * 4) = w;
    }
    __syncthreads();

    // ---- epilogue stage 2: e_tile = zsm @ wsm, K = 128 ----
    float acc2[2][4][4];
#pragma unroll
    for (int i = 0; i < 2; i++)
#pragma unroll
        for (int j = 0; j < 4; j++)
#pragma unroll
            for (int k = 0; k < 4; k++) acc2[i][j][k] = 0.f;

#pragma unroll
    for (int kk = 0; kk < CC; kk += 8) {
        uint32_t af[2][4];
#pragma unroll
        for (int mt = 0; mt < 2; mt++) {
            const float* ap = zsm + (wm + mt * 16 + g) * LDZ + kk + tg;
            af[mt][0] = __float_as_uint(ap[0]);
            af[mt][1] = __float_as_uint(ap[8 * LDZ]);
            af[mt][2] = __float_as_uint(ap[4]);
            af[mt][3] = __float_as_uint(ap[8 * LDZ + 4]);
        }
#pragma unroll
        for (int nt = 0; nt < 4; nt++) {
            const float* bp = wsm + (kk + tg) * LDW + wn + nt * 8 + g;
            uint32_t b0 = __float_as_uint(bp[0]);
            uint32_t b1 = __float_as_uint(bp[4 * LDW]);
            mma8(acc2[0][nt][0], acc2[0][nt][1], acc2[0][nt][2], acc2[0][nt][3],
                 af[0][0], af[0][1], af[0][2], af[0][3], b0, b1);
            mma8(acc2[1][nt][0], acc2[1][nt][1], acc2[1][nt][2], acc2[1][nt][3],
                 af[1][0], af[1][1], af[1][2], af[1][3], b0, b1);
        }
    }

    // ---- epilogue stage 3: bias + zero-guard + store e ----
#pragma unroll
    for (int mt = 0; mt < 2; mt++) {
        int r0 = wm + mt * 16 + g;
        bool ok0 = s_rs[r0] > 0.f;
        bool ok1 = s_rs[r0 + 8] > 0.f;
        float* ep = g_E + ((size_t)(b * EE + e0 + r0)) * CC;
#pragma unroll
        for (int nt = 0; nt < 4; nt++) {
            int col = wn + nt * 8 + 2 * tg;
            float b0v = s_b[col], b1v = s_b[col + 1];
            float2 v0 = make_float2(ok0 ? acc2[mt][nt][0] + b0v : 0.f,
                                    ok0 ? acc2[mt][nt][1] + b1v : 0.f);
            float2 v1 = make_float2(ok1 ? acc2[mt][nt][2] + b0v : 0.f,
                                    ok1 ? acc2[mt][nt][3] + b1v : 0.f);
            *reinterpret_cast<float2*>(ep + col) = v0;
            *reinterpret_cast<float2*>(ep + (size_t)8 * CC + col) = v1;
        }
    }
}

// ===========================================================================
// S3: v[b,n,:] = (sum_e H[b,n,e] * e[b,e,:]) / sv[b,n]   (sv from A-frags)
// ===========================================================================
__global__ void __launch_bounds__(NT, 1)
s3_kernel(const float* __restrict__ H, float* __restrict__ out) {
    const int b  = blockIdx.y;
    const int n0 = blockIdx.x * BM;

    extern __shared__ float sm[];
    float* As = sm;                       // 2 * BM * LDMK ([m][k])
    float* Bs = sm + 2 * BM * LDMK;       // 2 * BK * LDB_
    __shared__ float s_rs[BM];
    __shared__ float s_inv[BM];

    const int tid = threadIdx.x;
    const int lane = tid & 31, wid = tid >> 5;
    const int g = lane >> 2, tg = lane & 3;
    const int wm = (wid >> 2) * 32;
    const int wn = (wid & 3) * 32;

    const float* Hb = H + (size_t)b * NN * EE;

    float acc[2][4][4];
#pragma unroll
    for (int i = 0; i < 2; i++)
#pragma unroll
        for (int j = 0; j < 4; j++)
#pragma unroll
            for (int k = 0; k < 4; k++) acc[i][j][k] = 0.f;
    float rs[2][2] = {{0.f, 0.f}, {0.f, 0.f}};

    float4 ar[2], br[2];

    auto LDGA = [&](int k0) {
#pragma unroll
        for (int i = 0; i < 2; i++) {
            int idx = tid + i * NT;
            int m = idx >> 3, k4 = idx & 7;
            ar[i] = *reinterpret_cast<const float4*>(Hb + (size_t)(n0 + m) * EE + k0 + k4 * 4);
        }
    };
    auto LDGB = [&](int k0) {
#pragma unroll
        for (int i = 0; i < 2; i++) {
            int idx = tid + i * NT;
            int k = idx >> 5, c4 = idx & 31;
            br[i] = *reinterpret_cast<const float4*>(g_E + (size_t)(b * EE + k0 + k) * CC + c4 * 4);
        }
    };
    auto STS = [&](int buf) {
        float* Ad = As + buf * BM * LDMK;
        float* Bd = Bs + buf * BK * LDB_;
#pragma unroll
        for (int i = 0; i < 2; i++) {
            int idx = tid + i * NT;
            int m = idx >> 3, k4 = idx & 7;
            *reinterpret_cast<float4*>(Ad + m * LDMK + k4 * 4) = ar[i];  // H exact
            int k = idx >> 5, c4 = idx & 31;
            float4 v = br[i];
            v.x = tf32r(v.x); v.y = tf32r(v.y); v.z = tf32r(v.z); v.w = tf32r(v.w);
            *reinterpret_cast<float4*>(Bd + k * LDB_ + c4 * 4) = v;
        }
    };
    auto COMPUTE = [&](int buf) {
        const float* Ab = As + buf * BM * LDMK;
        const float* Bb = Bs + buf * BK * LDB_;
#pragma unroll
        for (int kk = 0; kk < BK; kk += 8) {
            uint32_t af[2][4];
#pragma unroll
            for (int mt = 0; mt < 2; mt++) {
                const float* ap = Ab + (wm + mt * 16 + g) * LDMK + kk + tg;
                af[mt][0] = __float_as_uint(ap[0]);
                af[mt][1] = __float_as_uint(ap[8 * LDMK]);
                af[mt][2] = __float_as_uint(ap[4]);
                af[mt][3] = __float_as_uint(ap[8 * LDMK + 4]);
            }
            if ((wid & 3) == 0) {
#pragma unroll
                for (int mt = 0; mt < 2; mt++) {
                    rs[mt][0] += __uint_as_float(af[mt][0]) + __uint_as_float(af[mt][2]);
                    rs[mt][1] += __uint_as_float(af[mt][1]) + __uint_as_float(af[mt][3]);
                }
            }
#pragma unroll
            for (int nt = 0; nt < 4; nt++) {
                const float* bp = Bb + (kk + tg) * LDB_ + wn + nt * 8 + g;
                uint32_t b0 = __float_as_uint(bp[0]);
                uint32_t b1 = __float_as_uint(bp[4 * LDB_]);
                mma8(acc[0][nt][0], acc[0][nt][1], acc[0][nt][2], acc[0][nt][3],
                     af[0][0], af[0][1], af[0][2], af[0][3], b0, b1);
                mma8(acc[1][nt][0], acc[1][nt][1], acc[1][nt][2], acc[1][nt][3],
                     af[1][0], af[1][1], af[1][2], af[1][3], b0, b1);
            }
        }
    };

    LDGA(0); LDGB(0); STS(0); __syncthreads();
    int buf = 0;
    const int KT = EE / BK;
    for (int kt = 0; kt < KT; kt++) {
        if (kt + 1 < KT) { LDGA((kt + 1) * BK); LDGB((kt + 1) * BK); }
        COMPUTE(buf);
        if (kt + 1 < KT) {
            STS(buf ^ 1);
            __syncthreads();
            buf ^= 1;
        }
    }

    if ((wid & 3) == 0) {
#pragma unroll
        for (int mt = 0; mt < 2; mt++)
#pragma unroll
            for (int j = 0; j < 2; j++) {
                float v = rs[mt][j];
                v += __shfl_xor_sync(0xffffffff, v, 1);
                v += __shfl_xor_sync(0xffffffff, v, 2);
                if (tg == 0) s_rs[wm + mt * 16 + j * 8 + g] = v;
            }
    }
    __syncthreads();
    if (tid < BM) {
        float s = s_rs[tid];
        s_inv[tid] = (s > 0.f) ? (1.0f / s) : 0.f;
    }
    __syncthreads();

#pragma unroll
    for (int mt = 0; mt < 2; mt++) {
        int r0 = wm + mt * 16 + g;
        float i0 = s_inv[r0], i1 = s_inv[r0 + 8];
        float* op = out + ((size_t)(b * NN + n0 + r0)) * CC;
#pragma unroll
        for (int nt = 0; nt < 4; nt++) {
            int col = wn + nt * 8 + 2 * tg;
            float2 v0 = make_float2(acc[mt][nt][0] * i0, acc[mt][nt][1] * i0);
            float2 v1 = make_float2(acc[mt][nt][2] * i1, acc[mt][nt][3] * i1);
            *reinterpret_cast<float2*>(op + col) = v0;
            *reinterpret_cast<float2*>(op + (size_t)8 * CC + col) = v1;
        }
    }
}

// ===========================================================================
extern "C" void kernel_launch(void* const* d_in, const int* in_sizes, int n_in,
                              void* d_out, int out_size) {
    const float* X = nullptr;   // 8*4096*128  = 4194304
    const float* H = nullptr;   // 8*4096*2048 = 67108864
    const float* W = nullptr;   // 128*128     = 16384
    const float* bias = nullptr;// 128
    for (int i = 0; i < n_in; i++) {
        if (in_sizes[i] == BB * NN * CC)      X = (const float*)d_in[i];
        else if (in_sizes[i] == BB * NN * EE) H = (const float*)d_in[i];
        else if (in_sizes[i] == CC * CC)      W = (const float*)d_in[i];
        else if (in_sizes[i] == CC)           bias = (const float*)d_in[i];
    }
    float* out = (float*)d_out;

    // s1 smem: max(main loop, epilogue overlay)
    const int smem_main = (2 * BK * LDKM + 2 * BK * LDB_) * (int)sizeof(float);  // 69632
    const int smem_epi  = (BM * LDZ + CC * LDW) * (int)sizeof(float);            // 137216
    const int smem1 = (smem_main > smem_epi) ? smem_main : smem_epi;
    const int smem3 = (2 * BM * LDMK + 2 * BK * LDB_) * (int)sizeof(float);      // 71680

    cudaFuncSetAttribute(s1_kernel, cudaFuncAttributeMaxDynamicSharedMemorySize, smem1);
    cudaFuncSetAttribute(s3_kernel, cudaFuncAttributeMaxDynamicSharedMemorySize, smem3);

    s1_kernel<<<dim3(EE / BM, BB), NT, smem1>>>(H, X, W, bias);
    s3_kernel<<<dim3(NN / BM, BB), NT, smem3>>>(H, out);
}

// round 12
// speedup vs baseline: 1.0131x; 1.0131x over previous
#include <cuda_runtime.h>
#include <cstdint>
#include <cstddef>

// Problem shape (fixed)
#define BB 8
#define NN 4096
#define EE 2048
#define CC 128

// Scratch (no cudaMalloc allowed)
__device__ float g_E[BB * EE * CC];   // e (edge features), produced by fused s1

// GEMM tiling
#define BM 128
#define BN 128
#define BK 32
#define LDKM 136   // As stored [k][m], pad 8 (≡8 mod 32) -> conflict-free a-frag loads
#define LDMK 36    // As stored [m][k], pad 4 (≡4 mod 32) -> conflict-free a-frag loads
#define LDB_ 136   // Bs stored [k][n], pad 8 -> conflict-free b-frag loads
#define LDZ  132   // epilogue z smem [m][k], K=128, pad 4
#define LDW  136   // epilogue W smem [k][n], pad 8

// Threads: 512 = 16 warps, warp grid 4(m) x 4(n); each warp computes 32x32.
#define NT 512

__device__ __forceinline__ float tf32r(float x) {
    uint32_t u;
    asm("cvt.rna.tf32.f32 %0, %1;" : "=r"(u) : "f"(x));
    return __uint_as_float(u);
}

__device__ __forceinline__ void mma8(float& d0, float& d1, float& d2, float& d3,
                                     uint32_t a0, uint32_t a1, uint32_t a2, uint32_t a3,
                                     uint32_t b0, uint32_t b1) {
    asm volatile(
        "mma.sync.aligned.m16n8k8.row.col.f32.tf32.tf32.f32 "
        "{%0,%1,%2,%3},{%4,%5,%6,%7},{%8,%9},{%0,%1,%2,%3};"
        : "+f"(d0), "+f"(d1), "+f"(d2), "+f"(d3)
        : "r"(a0), "r"(a1), "r"(a2), "r"(a3), "r"(b0), "r"(b1));
}

// ===========================================================================
// S1 (fused with S2):
//   z[b,e,:] = sum_n H[b,n,e] * x[b,n,:]       (A = H^T, tensor cores)
//   se[b,e]  = sum_n H[b,n,e]                  (free from A-fragments)
//   e[b,e,:] = se>0 ? (z/se) @ W + bias : 0    (epilogue GEMM, K=128)
// ===========================================================================
__global__ void __launch_bounds__(NT, 1)
s1_kernel(const float* __restrict__ H, const float* __restrict__ X,
          const float* __restrict__ Wm, const float* __restrict__ bias) {
    const int b  = blockIdx.y;
    const int e0 = blockIdx.x * BM;

    extern __shared__ float sm[];
    // main loop overlay
    float* As = sm;                       // 2 * BK * LDKM  ([k][m])
    float* Bs = sm + 2 * BK * LDKM;       // 2 * BK * LDB_  ([k][n])
    // epilogue overlay (reuses the same bytes)
    float* zsm = sm;                      // BM * LDZ   ([m][k])  16896 floats
    float* wsm = sm + BM * LDZ;           // CC * LDW   ([k][n])  17408 floats
    __shared__ float s_rs[BM];
    __shared__ float s_inv[BM];
    __shared__ float s_b[CC];

    const int tid = threadIdx.x;
    const int lane = tid & 31, wid = tid >> 5;
    const int g = lane >> 2, tg = lane & 3;
    const int wm = (wid >> 2) * 32;       // 4 m-groups
    const int wn = (wid & 3) * 32;        // 4 n-groups

    if (tid < CC) s_b[tid] = bias[tid];

    const float* Hb = H + (size_t)b * NN * EE;
    const float* Xb = X + (size_t)b * NN * CC;

    float acc[2][4][4];
#pragma unroll
    for (int i = 0; i < 2; i++)
#pragma unroll
        for (int j = 0; j < 4; j++)
#pragma unroll
            for (int k = 0; k < 4; k++) acc[i][j][k] = 0.f;
    float rs[2][2] = {{0.f, 0.f}, {0.f, 0.f}};

    float4 ar[2], br[2];

    auto LDGA = [&](int n0) {
#pragma unroll
        for (int i = 0; i < 2; i++) {
            int idx = tid + i * NT;
            int k = idx >> 5, m4 = idx & 31;
            ar[i] = *reinterpret_cast<const float4*>(Hb + (size_t)(n0 + k) * EE + e0 + m4 * 4);
        }
    };
    auto LDGB = [&](int n0) {
#pragma unroll
        for (int i = 0; i < 2; i++) {
            int idx = tid + i * NT;
            int k = idx >> 5, c4 = idx & 31;
            br[i] = *reinterpret_cast<const float4*>(Xb + (size_t)(n0 + k) * CC + c4 * 4);
        }
    };
    auto STS = [&](int buf) {
        float* Ad = As + buf * BK * LDKM;
        float* Bd = Bs + buf * BK * LDB_;
#pragma unroll
        for (int i = 0; i < 2; i++) {
            int idx = tid + i * NT;
            int k = idx >> 5, m4 = idx & 31;
            *reinterpret_cast<float4*>(Ad + k * LDKM + m4 * 4) = ar[i];  // H exact, no cvt
            float4 v = br[i];
            v.x = tf32r(v.x); v.y = tf32r(v.y); v.z = tf32r(v.z); v.w = tf32r(v.w);
            *reinterpret_cast<float4*>(Bd + k * LDB_ + m4 * 4) = v;
        }
    };
    auto COMPUTE = [&](int buf) {
        const float* Ab = As + buf * BK * LDKM;
        const float* Bb = Bs + buf * BK * LDB_;
#pragma unroll
        for (int kk = 0; kk < BK; kk += 8) {
            uint32_t af[2][4];
#pragma unroll
            for (int mt = 0; mt < 2; mt++) {
                const float* ap = Ab + (kk + tg) * LDKM + wm + mt * 16 + g;
                af[mt][0] = __float_as_uint(ap[0]);
                af[mt][1] = __float_as_uint(ap[8]);
                af[mt][2] = __float_as_uint(ap[4 * LDKM]);
                af[mt][3] = __float_as_uint(ap[4 * LDKM + 8]);
            }
            if ((wid & 3) == 0) {  // count each H element once (wn==0 warps)
#pragma unroll
                for (int mt = 0; mt < 2; mt++) {
                    rs[mt][0] += __uint_as_float(af[mt][0]) + __uint_as_float(af[mt][2]);
                    rs[mt][1] += __uint_as_float(af[mt][1]) + __uint_as_float(af[mt][3]);
                }
            }
#pragma unroll
            for (int nt = 0; nt < 4; nt++) {
                const float* bp = Bb + (kk + tg) * LDB_ + wn + nt * 8 + g;
                uint32_t b0 = __float_as_uint(bp[0]);
                uint32_t b1 = __float_as_uint(bp[4 * LDB_]);
                mma8(acc[0][nt][0], acc[0][nt][1], acc[0][nt][2], acc[0][nt][3],
                     af[0][0], af[0][1], af[0][2], af[0][3], b0, b1);
                mma8(acc[1][nt][0], acc[1][nt][1], acc[1][nt][2], acc[1][nt][3],
                     af[1][0], af[1][1], af[1][2], af[1][3], b0, b1);
            }
        }
    };

    LDGA(0); LDGB(0); STS(0); __syncthreads();
    int buf = 0;
    const int KT = NN / BK;
    for (int kt = 0; kt < KT; kt++) {
        if (kt + 1 < KT) { LDGA((kt + 1) * BK); LDGB((kt + 1) * BK); }
        COMPUTE(buf);
        if (kt + 1 < KT) {
            STS(buf ^ 1);
            __syncthreads();
            buf ^= 1;
        }
    }

    // se: quad-reduce row sums (only wn==0 warps carried them)
    if ((wid & 3) == 0) {
#pragma unroll
        for (int mt = 0; mt < 2; mt++)
#pragma unroll
            for (int j = 0; j < 2; j++) {
                float v = rs[mt][j];
                v += __shfl_xor_sync(0xffffffff, v, 1);
                v += __shfl_xor_sync(0xffffffff, v, 2);
                if (tg == 0) s_rs[wm + mt * 16 + j * 8 + g] = v;
            }
    }
    __syncthreads();
    if (tid < BM) {
        float s = s_rs[tid];
        s_inv[tid] = (s > 0.f) ? (1.0f / s) : 0.f;
    }
    __syncthreads();   // also: all warps done reading As/Bs before overlay reuse

    // ---- epilogue stage 1: z/se -> zsm (tf32), W -> wsm (tf32) ----
#pragma unroll
    for (int mt = 0; mt < 2; mt++) {
        int r0 = wm + mt * 16 + g;
        float i0 = s_inv[r0], i1 = s_inv[r0 + 8];
#pragma unroll
        for (int nt = 0; nt < 4; nt++) {
            int col = wn + nt * 8 + 2 * tg;
            float2 v0 = make_float2(tf32r(acc[mt][nt][0] * i0), tf32r(acc[mt][nt][1] * i0));
            float2 v1 = make_float2(tf32r(acc[mt][nt][2] * i1), tf32r(acc[mt][nt][3] * i1));
            *reinterpret_cast<float2*>(zsm + r0 * LDZ + col) = v0;
            *reinterpret_cast<float2*>(zsm + (r0 + 8) * LDZ + col) = v1;
        }
    }
#pragma unroll
    for (int i = 0; i < (CC * CC / 4) / NT; i++) {   // 8 iters
        int idx = tid + i * NT;
        int k = idx >> 5, n4 = idx & 31;
        float4 w = *reinterpret_cast<const float4*>(Wm + (size_t)k * CC + n4 * 4);
        w.x = tf32r(w.x); w.y = tf32r(w.y); w.z = tf32r(w.z); w.w = tf32r(w.w);
        *reinterpret_cast<float4*>(wsm + k * LDW + n4 * 4) = w;
    }
    __syncthreads();

    // ---- epilogue stage 2: e_tile = zsm @ wsm, K = 128 ----
    float acc2[2][4][4];
#pragma unroll
    for (int i = 0; i < 2; i++)
#pragma unroll
        for (int j = 0; j < 4; j++)
#pragma unroll
            for (int k = 0; k < 4; k++) acc2[i][j][k] = 0.f;

#pragma unroll
    for (int kk = 0; kk < CC; kk += 8) {
        uint32_t af[2][4];
#pragma unroll
        for (int mt = 0; mt < 2; mt++) {
            const float* ap = zsm + (wm + mt * 16 + g) * LDZ + kk + tg;
            af[mt][0] = __float_as_uint(ap[0]);
            af[mt][1] = __float_as_uint(ap[8 * LDZ]);
            af[mt][2] = __float_as_uint(ap[4]);
            af[mt][3] = __float_as_uint(ap[8 * LDZ + 4]);
        }
#pragma unroll
        for (int nt = 0; nt < 4; nt++) {
            const float* bp = wsm + (kk + tg) * LDW + wn + nt * 8 + g;
            uint32_t b0 = __float_as_uint(bp[0]);
            uint32_t b1 = __float_as_uint(bp[4 * LDW]);
            mma8(acc2[0][nt][0], acc2[0][nt][1], acc2[0][nt][2], acc2[0][nt][3],
                 af[0][0], af[0][1], af[0][2], af[0][3], b0, b1);
            mma8(acc2[1][nt][0], acc2[1][nt][1], acc2[1][nt][2], acc2[1][nt][3],
                 af[1][0], af[1][1], af[1][2], af[1][3], b0, b1);
        }
    }

    // ---- epilogue stage 3: bias + zero-guard + store e ----
#pragma unroll
    for (int mt = 0; mt < 2; mt++) {
        int r0 = wm + mt * 16 + g;
        bool ok0 = s_rs[r0] > 0.f;
        bool ok1 = s_rs[r0 + 8] > 0.f;
        float* ep = g_E + ((size_t)(b * EE + e0 + r0)) * CC;
#pragma unroll
        for (int nt = 0; nt < 4; nt++) {
            int col = wn + nt * 8 + 2 * tg;
            float b0v = s_b[col], b1v = s_b[col + 1];
            float2 v0 = make_float2(ok0 ? acc2[mt][nt][0] + b0v : 0.f,
                                    ok0 ? acc2[mt][nt][1] + b1v : 0.f);
            float2 v1 = make_float2(ok1 ? acc2[mt][nt][2] + b0v : 0.f,
                                    ok1 ? acc2[mt][nt][3] + b1v : 0.f);
            *reinterpret_cast<float2*>(ep + col) = v0;
            *reinterpret_cast<float2*>(ep + (size_t)8 * CC + col) = v1;
        }
    }
}

// ===========================================================================
// S3: v[b,n,:] = (sum_e H[b,n,e] * e[b,e,:]) / sv[b,n]   (sv from A-frags)
// ===========================================================================
__global__ void __launch_bounds__(NT, 1)
s3_kernel(const float* __restrict__ H, float* __restrict__ out) {
    const int b  = blockIdx.y;
    const int n0 = blockIdx.x * BM;

    extern __shared__ float sm[];
    float* As = sm;                       // 2 * BM * LDMK ([m][k])
    float* Bs = sm + 2 * BM * LDMK;       // 2 * BK * LDB_
    __shared__ float s_rs[BM];
    __shared__ float s_inv[BM];

    const int tid = threadIdx.x;
    const int lane = tid & 31, wid = tid >> 5;
    const int g = lane >> 2, tg = lane & 3;
    const int wm = (wid >> 2) * 32;
    const int wn = (wid & 3) * 32;

    const float* Hb = H + (size_t)b * NN * EE;

    float acc[2][4][4];
#pragma unroll
    for (int i = 0; i < 2; i++)
#pragma unroll
        for (int j = 0; j < 4; j++)
#pragma unroll
            for (int k = 0; k < 4; k++) acc[i][j][k] = 0.f;
    float rs[2][2] = {{0.f, 0.f}, {0.f, 0.f}};

    float4 ar[2], br[2];

    auto LDGA = [&](int k0) {
#pragma unroll
        for (int i = 0; i < 2; i++) {
            int idx = tid + i * NT;
            int m = idx >> 3, k4 = idx & 7;
            ar[i] = *reinterpret_cast<const float4*>(Hb + (size_t)(n0 + m) * EE + k0 + k4 * 4);
        }
    };
    auto LDGB = [&](int k0) {
#pragma unroll
        for (int i = 0; i < 2; i++) {
            int idx = tid + i * NT;
            int k = idx >> 5, c4 = idx & 31;
            br[i] = *reinterpret_cast<const float4*>(g_E + (size_t)(b * EE + k0 + k) * CC + c4 * 4);
        }
    };
    auto STS = [&](int buf) {
        float* Ad = As + buf * BM * LDMK;
        float* Bd = Bs + buf * BK * LDB_;
#pragma unroll
        for (int i = 0; i < 2; i++) {
            int idx = tid + i * NT;
            int m = idx >> 3, k4 = idx & 7;
            *reinterpret_cast<float4*>(Ad + m * LDMK + k4 * 4) = ar[i];  // H exact
            int k = idx >> 5, c4 = idx & 31;
            float4 v = br[i];
            v.x = tf32r(v.x); v.y = tf32r(v.y); v.z = tf32r(v.z); v.w = tf32r(v.w);
            *reinterpret_cast<float4*>(Bd + k * LDB_ + c4 * 4) = v;
        }
    };
    auto COMPUTE = [&](int buf) {
        const float* Ab = As + buf * BM * LDMK;
        const float* Bb = Bs + buf * BK * LDB_;
#pragma unroll
        for (int kk = 0; kk < BK; kk += 8) {
            uint32_t af[2][4];
#pragma unroll
            for (int mt = 0; mt < 2; mt++) {
                const float* ap = Ab + (wm + mt * 16 + g) * LDMK + kk + tg;
                af[mt][0] = __float_as_uint(ap[0]);
                af[mt][1] = __float_as_uint(ap[8 * LDMK]);
                af[mt][2] = __float_as_uint(ap[4]);
                af[mt][3] = __float_as_uint(ap[8 * LDMK + 4]);
            }
            if ((wid & 3) == 0) {
#pragma unroll
                for (int mt = 0; mt < 2; mt++) {
                    rs[mt][0] += __uint_as_float(af[mt][0]) + __uint_as_float(af[mt][2]);
                    rs[mt][1] += __uint_as_float(af[mt][1]) + __uint_as_float(af[mt][3]);
                }
            }
#pragma unroll
            for (int nt = 0; nt < 4; nt++) {
                const float* bp = Bb + (kk + tg) * LDB_ + wn + nt * 8 + g;
                uint32_t b0 = __float_as_uint(bp[0]);
                uint32_t b1 = __float_as_uint(bp[4 * LDB_]);
                mma8(acc[0][nt][0], acc[0][nt][1], acc[0][nt][2], acc[0][nt][3],
                     af[0][0], af[0][1], af[0][2], af[0][3], b0, b1);
                mma8(acc[1][nt][0], acc[1][nt][1], acc[1][nt][2], acc[1][nt][3],
                     af[1][0], af[1][1], af[1][2], af[1][3], b0, b1);
            }
        }
    };

    LDGA(0); LDGB(0); STS(0); __syncthreads();
    int buf = 0;
    const int KT = EE / BK;
    for (int kt = 0; kt < KT; kt++) {
        if (kt + 1 < KT) { LDGA((kt + 1) * BK); LDGB((kt + 1) * BK); }
        COMPUTE(buf);
        if (kt + 1 < KT) {
            STS(buf ^ 1);
            __syncthreads();
            buf ^= 1;
        }
    }

    if ((wid & 3) == 0) {
#pragma unroll
        for (int mt = 0; mt < 2; mt++)
#pragma unroll
            for (int j = 0; j < 2; j++) {
                float v = rs[mt][j];
                v += __shfl_xor_sync(0xffffffff, v, 1);
                v += __shfl_xor_sync(0xffffffff, v, 2);
                if (tg == 0) s_rs[wm + mt * 16 + j * 8 + g] = v;
            }
    }
    __syncthreads();
    if (tid < BM) {
        float s = s_rs[tid];
        s_inv[tid] = (s > 0.f) ? (1.0f / s) : 0.f;
    }
    __syncthreads();

#pragma unroll
    for (int mt = 0; mt < 2; mt++) {
        int r0 = wm + mt * 16 + g;
        float i0 = s_inv[r0], i1 = s_inv[r0 + 8];
        float* op = out + ((size_t)(b * NN + n0 + r0)) * CC;
#pragma unroll
        for (int nt = 0; nt < 4; nt++) {
            int col = wn + nt * 8 + 2 * tg;
            float2 v0 = make_float2(acc[mt][nt][0] * i0, acc[mt][nt][1] * i0);
            float2 v1 = make_float2(acc[mt][nt][2] * i1, acc[mt][nt][3] * i1);
            *reinterpret_cast<float2*>(op + col) = v0;
            *reinterpret_cast<float2*>(op + (size_t)8 * CC + col) = v1;
        }
    }
}

// ===========================================================================
extern "C" void kernel_launch(void* const* d_in, const int* in_sizes, int n_in,
                              void* d_out, int out_size) {
    const float* X = nullptr;   // 8*4096*128  = 4194304
    const float* H = nullptr;   // 8*4096*2048 = 67108864
    const float* W = nullptr;   // 128*128     = 16384
    const float* bias = nullptr;// 128
    for (int i = 0; i < n_in; i++) {
        if (in_sizes[i] == BB * NN * CC)      X = (const float*)d_in[i];
        else if (in_sizes[i] == BB * NN * EE) H = (const float*)d_in[i];
        else if (in_sizes[i] == CC * CC)      W = (const float*)d_in[i];
        else if (in_sizes[i] == CC)           bias = (const float*)d_in[i];
    }
    float* out = (float*)d_out;

    // s1 smem: max(main loop, epilogue overlay)
    const int smem_main = (2 * BK * LDKM + 2 * BK * LDB_) * (int)sizeof(float);  // 69632
    const int smem_epi  = (BM * LDZ + CC * LDW) * (int)sizeof(float);            // 137216
    const int smem1 = (smem_main > smem_epi) ? smem_main : smem_epi;
    const int smem3 = (2 * BM * LDMK + 2 * BK * LDB_) * (int)sizeof(float);      // 71680

    cudaFuncSetAttribute(s1_kernel, cudaFuncAttributeMaxDynamicSharedMemorySize, smem1);
    cudaFuncSetAttribute(s3_kernel, cudaFuncAttributeMaxDynamicSharedMemorySize, smem3);

    s1_kernel<<<dim3(EE / BM, BB), NT, smem1>>>(H, X, W, bias);
    s3_kernel<<<dim3(NN / BM, BB), NT, smem3>>>(H, out);
}